// round 14
// baseline (speedup 1.0000x reference)
#include <cuda_runtime.h>
#include <cuda_fp16.h>
#include <cstdint>
#include <math.h>

// Problem constants
#define BB 4
#define NN 2048
#define DD 512
#define HH 8
#define HD 64
#define NC 2048
#define RR (BB*NN)

// Scratch (device globals; no allocation allowed)
__device__ __half g_xnh[(size_t)RR * DD];   // half: layernorm(x); later o_input
__device__ __half g_mmh[(size_t)RR * NC];   // half: silu(xn @ uvqk) [u|v|q|k]
__device__ __half g_wh [(size_t)NC * DD];   // half: uvqk transposed [n][k]
__device__ __half g_owh[(size_t)DD * DD];   // half: o_weight [n][k]
__device__ __half g_ath[(size_t)RR * DD];   // half attention output

__device__ __forceinline__ float silu_f(float v) {
    return v / (1.0f + __expf(-v));
}

// silu on a packed pair via tanh.approx.f16x2 (1 MUFU per 2 values)
__device__ __forceinline__ uint32_t silu_h2(float a, float b) {
    __half2 s = __floats2half2_rn(a, b);
    const __half2 hhalf = __floats2half2_rn(0.5f, 0.5f);
    __half2 hs = __hmul2(s, hhalf);
    uint32_t hsu = *(uint32_t*)&hs;
    uint32_t t;
    asm("tanh.approx.f16x2 %0, %1;" : "=r"(t) : "r"(hsu));
    __half2 th = *(__half2*)&t;
    __half2 sig = __hfma2(th, hhalf, hhalf);
    __half2 o = __hmul2(s, sig);
    return *(uint32_t*)&o;
}

__device__ __forceinline__ uint32_t smem_u32(const void* p) {
    uint32_t a;
    asm("{ .reg .u64 t; cvta.to.shared.u64 t, %1; cvt.u32.u64 %0, t; }"
        : "=r"(a) : "l"(p));
    return a;
}

__device__ __forceinline__ void ldmA(uint32_t* a, uint32_t addr) {
    asm volatile("ldmatrix.sync.aligned.m8n8.x4.shared.b16 {%0,%1,%2,%3}, [%4];"
                 : "=r"(a[0]), "=r"(a[1]), "=r"(a[2]), "=r"(a[3]) : "r"(addr));
}

__device__ __forceinline__ void ldmT(uint32_t* a, uint32_t addr) {
    asm volatile("ldmatrix.sync.aligned.m8n8.x4.trans.shared.b16 {%0,%1,%2,%3}, [%4];"
                 : "=r"(a[0]), "=r"(a[1]), "=r"(a[2]), "=r"(a[3]) : "r"(addr));
}

// fp16 mma, fp32 accumulate: D += A(16x16) * B(16x8)
__device__ __forceinline__ void mma_f16(float* d, const uint32_t* a,
                                        uint32_t b0, uint32_t b1) {
    asm volatile(
        "mma.sync.aligned.m16n8k16.row.col.f32.f16.f16.f32 "
        "{%0,%1,%2,%3},{%4,%5,%6,%7},{%8,%9},{%0,%1,%2,%3};"
        : "+f"(d[0]), "+f"(d[1]), "+f"(d[2]), "+f"(d[3])
        : "r"(a[0]), "r"(a[1]), "r"(a[2]), "r"(a[3]), "r"(b0), "r"(b1));
}

__device__ __forceinline__ void cp16(uint32_t dst, const void* src) {
    asm volatile("cp.async.cg.shared.global [%0], [%1], 16;" :: "r"(dst), "l"(src));
}
#define CP_COMMIT() asm volatile("cp.async.commit_group;" ::: "memory")
#define CP_WAIT(n)  asm volatile("cp.async.wait_group %0;" :: "n"(n) : "memory")

// ldmatrix-x4 per-lane byte offset for a 16x16-half A block, stride in halfs
__device__ __forceinline__ uint32_t ldm_off_h(int lane, int stride_halfs) {
    int r = (lane & 7) + ((lane >> 3) & 1) * 8;
    int c16 = (lane >> 4);
    return (uint32_t)(r * stride_halfs * 2 + c16 * 16);
}

// ldmatrix-x4 per-lane byte offset for B (K-major [n][k]): 2 n-frags x k16.
__device__ __forceinline__ uint32_t ldm_off_b(int lane, int stride_halfs) {
    int r = lane & 7;
    int m = lane >> 3;
    return (uint32_t)(((m >> 1) * 8 + r) * stride_halfs * 2 + (m & 1) * 16);
}

// ---------------------------------------------------------------------------
// LayerNorm: fp32 math, half output
// ---------------------------------------------------------------------------
__global__ void ln_kernel(const float* __restrict__ x) {
    int row = blockIdx.x;
    int t = threadIdx.x;
    float4 v = ((const float4*)(x + (size_t)row * DD))[t];
    float s  = v.x + v.y + v.z + v.w;
    float s2 = v.x*v.x + v.y*v.y + v.z*v.z + v.w*v.w;
#pragma unroll
    for (int o = 16; o > 0; o >>= 1) {
        s  += __shfl_xor_sync(0xffffffffu, s,  o);
        s2 += __shfl_xor_sync(0xffffffffu, s2, o);
    }
    __shared__ float sh[8];
    if ((t & 31) == 0) { sh[t >> 5] = s; sh[4 + (t >> 5)] = s2; }
    __syncthreads();
    s  = sh[0] + sh[1] + sh[2] + sh[3];
    s2 = sh[4] + sh[5] + sh[6] + sh[7];
    float mu  = s * (1.0f / DD);
    float var = fmaxf(s2 * (1.0f / DD) - mu * mu, 0.0f);
    float r   = rsqrtf(var + 1e-6f);
    __half2 h0 = __floats2half2_rn((v.x - mu) * r, (v.y - mu) * r);
    __half2 h1 = __floats2half2_rn((v.z - mu) * r, (v.w - mu) * r);
    ((__half2*)(g_xnh + (size_t)row * DD))[2 * t]     = h0;
    ((__half2*)(g_xnh + (size_t)row * DD))[2 * t + 1] = h1;
}

// Gated LN: reads half attention output, fp32 stats, half result
__global__ void gated_ln_kernel() {
    int row = blockIdx.x;
    int t = threadIdx.x;
    __half2 a01 = ((const __half2*)(g_ath + (size_t)row * DD))[2 * t];
    __half2 a23 = ((const __half2*)(g_ath + (size_t)row * DD))[2 * t + 1];
    float2 f0 = __half22float2(a01), f1 = __half22float2(a23);
    float s  = f0.x + f0.y + f1.x + f1.y;
    float s2 = f0.x*f0.x + f0.y*f0.y + f1.x*f1.x + f1.y*f1.y;
#pragma unroll
    for (int o = 16; o > 0; o >>= 1) {
        s  += __shfl_xor_sync(0xffffffffu, s,  o);
        s2 += __shfl_xor_sync(0xffffffffu, s2, o);
    }
    __shared__ float sh[8];
    if ((t & 31) == 0) { sh[t >> 5] = s; sh[4 + (t >> 5)] = s2; }
    __syncthreads();
    s  = sh[0] + sh[1] + sh[2] + sh[3];
    s2 = sh[4] + sh[5] + sh[6] + sh[7];
    float mu  = s * (1.0f / DD);
    float var = fmaxf(s2 * (1.0f / DD) - mu * mu, 0.0f);
    float r   = rsqrtf(var + 1e-6f);
    __half2 u01 = ((const __half2*)(g_mmh + (size_t)row * NC))[2 * t];
    __half2 u23 = ((const __half2*)(g_mmh + (size_t)row * NC))[2 * t + 1];
    float2 u0 = __half22float2(u01), u1 = __half22float2(u23);
    __half2 h0 = __floats2half2_rn(u0.x * (f0.x - mu) * r, u0.y * (f0.y - mu) * r);
    __half2 h1 = __floats2half2_rn(u1.x * (f1.x - mu) * r, u1.y * (f1.y - mu) * r);
    ((__half2*)(g_xnh + (size_t)row * DD))[2 * t]     = h0;
    ((__half2*)(g_xnh + (size_t)row * DD))[2 * t + 1] = h1;
}

// ---------------------------------------------------------------------------
// Weight converts
// ---------------------------------------------------------------------------
__global__ void cvt_w_t(const float* __restrict__ W) {
    __shared__ float tbuf[32][33];
    int lx = threadIdx.x & 31, ly = threadIdx.x >> 5;
    int bx = blockIdx.x, by = blockIdx.y;
    int col = bx * 32 + lx;
#pragma unroll
    for (int i = 0; i < 32; i += 8)
        tbuf[ly + i][lx] = W[(size_t)(by * 32 + ly + i) * NC + col];
    __syncthreads();
    int ok = by * 32 + lx;
#pragma unroll
    for (int i = 0; i < 32; i += 8)
        g_wh[(size_t)(bx * 32 + ly + i) * DD + ok] = __float2half_rn(tbuf[lx][ly + i]);
}

__global__ void cvt_ow(const float* __restrict__ W) {
    int i = blockIdx.x * 256 + threadIdx.x;
    float4 v = ((const float4*)W)[i];
    __half2 h0 = __floats2half2_rn(v.x, v.y);
    __half2 h1 = __floats2half2_rn(v.z, v.w);
    ((__half2*)g_owh)[2 * i]     = h0;
    ((__half2*)g_owh)[2 * i + 1] = h1;
}

// ---------------------------------------------------------------------------
// fp16 mma GEMM: 3-stage cp.async pipeline, one sync per K-chunk.
// ---------------------------------------------------------------------------
#define SAH   72
#define ASBH  (128 * SAH * 2)              // 18432 per stage
#define GSMEMH (6 * ASBH)                  // A[3] + B[3] = 110592

template <int MODE>
__global__ __launch_bounds__(256)
void gemm_h(const __half* __restrict__ A, const __half* __restrict__ Bm,
            __half* __restrict__ Ch, float* __restrict__ Cf,
            const float* __restrict__ bias, const float* __restrict__ xres,
            int Nn, int K) {
    extern __shared__ char smem[];
    uint32_t sAu = smem_u32(smem);
    uint32_t sBu = sAu + 3 * ASBH;

    int tid = threadIdx.x;
    int wid = tid >> 5, lane = tid & 31;
    int m0 = blockIdx.y * 128, n0 = blockIdx.x * 128;
    int wm = (wid & 1) * 64;
    int wn = (wid >> 1) * 32;

    float acc[4][4][4];
#pragma unroll
    for (int i = 0; i < 4; i++)
#pragma unroll
        for (int j = 0; j < 4; j++)
#pragma unroll
            for (int r = 0; r < 4; r++) acc[i][j][r] = 0.0f;

    const int NCH = K / 64;
    uint32_t aoff = ldm_off_h(lane, SAH);
    uint32_t boff = (uint32_t)(wn * SAH * 2) + ldm_off_b(lane, SAH);

    auto stageA = [&](int c, int s) {
#pragma unroll
        for (int i = 0; i < 4; i++) {
            int idx = tid + i * 256;
            int row = idx >> 3, seg = idx & 7;
            cp16(sAu + s * ASBH + (row * SAH + seg * 8) * 2,
                 A + (size_t)(m0 + row) * K + c * 64 + seg * 8);
        }
    };
    auto stageB = [&](int c, int s) {
#pragma unroll
        for (int i = 0; i < 4; i++) {
            int idx = tid + i * 256;
            int row = idx >> 3, seg = idx & 7;
            cp16(sBu + s * ASBH + (row * SAH + seg * 8) * 2,
                 Bm + (size_t)(n0 + row) * K + c * 64 + seg * 8);
        }
    };

    stageA(0, 0); stageB(0, 0); CP_COMMIT();
    stageA(1, 1); stageB(1, 1); CP_COMMIT();

    for (int c = 0; c < NCH; c++) {
        int s = c % 3;
        if (c + 1 < NCH) { CP_WAIT(1); } else { CP_WAIT(0); }
        __syncthreads();    // chunk c visible; all warps done with stage (c-1)%3
        if (c + 2 < NCH) {
            int sn = (c + 2) % 3;
            stageA(c + 2, sn); stageB(c + 2, sn); CP_COMMIT();
        }

#pragma unroll
        for (int ks = 0; ks < 4; ks++) {
            uint32_t b01[4], b23[4];
            ldmA(b01, sBu + s * ASBH + boff + ks * 32);
            ldmA(b23, sBu + s * ASBH + boff + 16 * SAH * 2 + ks * 32);
#pragma unroll
            for (int im = 0; im < 4; im++) {
                uint32_t a[4];
                ldmA(a, sAu + s * ASBH + (uint32_t)((wm + im * 16) * SAH * 2 + ks * 32) + aoff);
                mma_f16(acc[im][0], a, b01[0], b01[1]);
                mma_f16(acc[im][1], a, b01[2], b01[3]);
                mma_f16(acc[im][2], a, b23[0], b23[1]);
                mma_f16(acc[im][3], a, b23[2], b23[3]);
            }
        }
    }

    int er = lane >> 2, ec = (lane & 3) * 2;
#pragma unroll
    for (int im = 0; im < 4; im++) {
#pragma unroll
        for (int in = 0; in < 4; in++) {
            int row = m0 + wm + im * 16 + er;
            int col = n0 + wn + in * 8 + ec;
#pragma unroll
            for (int h = 0; h < 2; h++) {
                float v0 = acc[im][in][2 * h + 0];
                float v1 = acc[im][in][2 * h + 1];
                int rr = row + 8 * h;
                if (MODE == 0) {
                    *(uint32_t*)(Ch + (size_t)rr * Nn + col) = silu_h2(v0, v1);
                } else {
                    float2 bi = *(const float2*)(bias + col);
                    float2 xr = *(const float2*)(xres + (size_t)rr * Nn + col);
                    float2 o; o.x = v0 + bi.x + xr.x; o.y = v1 + bi.y + xr.y;
                    *(float2*)(Cf + (size_t)rr * Nn + col) = o;
                }
            }
        }
    }
}

// ---------------------------------------------------------------------------
// Fused causal silu-attention: q-tile 64, 128-col KV macro-tiles, fast silu.
// Round 14 change: the phase1->phase2 S-visibility barrier is a NAMED
// half-block barrier (each row-group of 4 warps syncs independently) —
// phase 2 of warp w only reads Ss rows written by warps sharing (wid&1).
// ---------------------------------------------------------------------------
#define SAT2  72
#define QT2B  (64 * SAT2 * 2)             // 9216
#define KV2B  (128 * SAT2 * 2)            // 18432
#define SST   136
#define SSB   (64 * SST * 2)              // 17408
#define AOFF_K2 QT2B
#define AOFF_V2 (QT2B + 2 * KV2B)
#define AOFF_S2 (QT2B + 4 * KV2B)
#define ASMEM2  (AOFF_S2 + SSB)           // 100352

__global__ __launch_bounds__(256)
void attn_mma() {
    extern __shared__ char smem[];
    __half* Ss = (__half*)(smem + AOFF_S2);
    uint32_t sbase = smem_u32(smem);
    uint32_t Qsu = sbase;
    uint32_t Ssu = sbase + AOFF_S2;

    int qt = (int)(gridDim.x - 1 - blockIdx.x);   // heavy blocks first
    int h = blockIdx.y, b = blockIdx.z;
    int tid = threadIdx.x;
    int wid = tid >> 5, lane = tid & 31;
    int wm  = (wid & 1) * 32;          // 2 row-groups over 64 q-rows
    int wn2 = (wid >> 1) * 32;         // 4 warps over 128 kv-cols (phase 1)
    int wnd = (wid >> 1) * 16;         // 4 warps over 64 d-cols (phase 2)
    int rbar = 1 + (wid & 1);          // named barrier per row-group
    const int qcol = 1024 + h * HD;
    const int kcol = 1536 + h * HD;
    const int vcol = 512 + h * HD;
    uint32_t aoffQ = ldm_off_h(lane, SAT2);
    uint32_t aoffS = ldm_off_h(lane, SST);
    uint32_t koff = (uint32_t)(wn2 * SAT2 * 2) + ldm_off_b(lane, SAT2);

    // V ldmatrix.x4.trans per-lane address pieces
    int tl = lane & 7;
    int tmi = lane >> 3;
    int tkr = (tmi & 1) * 8 + tl;
    int tnc = (tmi >> 1) * 8;

    auto stageQ = [&]() {
#pragma unroll
        for (int i = 0; i < 2; i++) {
            int idx = tid + i * 256;
            int row = idx >> 3, seg = idx & 7;
            cp16(Qsu + (row * SAT2 + seg * 8) * 2,
                 g_mmh + (size_t)(b * NN + qt * 64 + row) * NC + qcol + seg * 8);
        }
    };
    auto stageKV2 = [&](int kt2, int s) {
        uint32_t kd = sbase + AOFF_K2 + s * KV2B;
        uint32_t vd = sbase + AOFF_V2 + s * KV2B;
#pragma unroll
        for (int i = 0; i < 4; i++) {
            int idx = tid + i * 256;
            int row = idx >> 3, seg = idx & 7;
            size_t gb = (size_t)(b * NN + kt2 * 128 + row) * NC;
            uint32_t so = (uint32_t)((row * SAT2 + seg * 8) * 2);
            cp16(kd + so, g_mmh + gb + kcol + seg * 8);
            cp16(vd + so, g_mmh + gb + vcol + seg * 8);
        }
    };

    float oacc[2][2][4];
#pragma unroll
    for (int i = 0; i < 2; i++)
#pragma unroll
        for (int j = 0; j < 2; j++)
#pragma unroll
            for (int r = 0; r < 4; r++) oacc[i][j][r] = 0.0f;

    const float inv_n = 1.0f / (float)NN;
    int er = lane >> 2, ec = (lane & 3) * 2;
    const int nkt2 = (qt + 2) >> 1;    // 128-col macro-tiles

    stageQ(); stageKV2(0, 0); CP_COMMIT();

    for (int kt2 = 0; kt2 < nkt2; kt2++) {
        int s = kt2 & 1;
        CP_WAIT(0);
        __syncthreads();   // macro-tile kt2 + all Ss reads of kt2-1 complete

        if (kt2 + 1 < nkt2) { stageKV2(kt2 + 1, s ^ 1); CP_COMMIT(); }

        uint32_t Ksu = sbase + AOFF_K2 + s * KV2B;
        uint32_t Vsu = sbase + AOFF_V2 + s * KV2B;

        // Phase 1: S[64 x 128] = Q @ K^T (warp: rows wm..+32 x cols wn2..+32)
        float sacc[2][4][4];
#pragma unroll
        for (int i = 0; i < 2; i++)
#pragma unroll
            for (int j = 0; j < 4; j++)
#pragma unroll
                for (int r = 0; r < 4; r++) sacc[i][j][r] = 0.0f;
#pragma unroll
        for (int ks = 0; ks < 4; ks++) {
            uint32_t a0[4], a1[4];
            ldmA(a0, Qsu + (uint32_t)(wm * SAT2 * 2 + ks * 32) + aoffQ);
            ldmA(a1, Qsu + (uint32_t)((wm + 16) * SAT2 * 2 + ks * 32) + aoffQ);
#pragma unroll
            for (int nb = 0; nb < 2; nb++) {
                uint32_t bk[4];
                ldmA(bk, Ksu + koff + (uint32_t)(nb * 16 * SAT2 * 2) + ks * 32);
                mma_f16(sacc[0][2 * nb + 0], a0, bk[0], bk[1]);
                mma_f16(sacc[0][2 * nb + 1], a0, bk[2], bk[3]);
                mma_f16(sacc[1][2 * nb + 0], a1, bk[0], bk[1]);
                mma_f16(sacc[1][2 * nb + 1], a1, bk[2], bk[3]);
            }
        }

        // mask (pre-silu; silu(0)==0) + fast silu -> Ss (stride 136)
        bool need_mask = (kt2 == nkt2 - 1);
#pragma unroll
        for (int im = 0; im < 2; im++) {
#pragma unroll
            for (int jn = 0; jn < 4; jn++) {
#pragma unroll
                for (int hh = 0; hh < 2; hh++) {
                    int i = wm + im * 16 + er + 8 * hh;
                    int j = wn2 + (jn >> 1) * 16 + (jn & 1) * 8 + ec;
                    float v0 = sacc[im][jn][2 * hh + 0];
                    float v1 = sacc[im][jn][2 * hh + 1];
                    if (need_mask) {
                        int ig = qt * 64 + i;
                        int jg = kt2 * 128 + j;
                        if (jg > ig) v0 = 0.0f;
                        if (jg + 1 > ig) v1 = 0.0f;
                    }
                    *(uint32_t*)(Ss + i * SST + j) = silu_h2(v0, v1);
                }
            }
        }
        // Named half-block barrier: only the 4 warps of this row-group wrote
        // the Ss rows this warp will read in phase 2.
        asm volatile("bar.sync %0, 128;" :: "r"(rbar) : "memory");

        // Phase 2: O += S @ V (k = 128 rows; warp covers d-cols wnd..wnd+16)
#pragma unroll
        for (int ks = 0; ks < 8; ks++) {
            uint32_t bv[4];
            ldmT(bv, Vsu + (uint32_t)(((ks * 16 + tkr) * SAT2 + wnd + tnc) * 2));
#pragma unroll
            for (int im = 0; im < 2; im++) {
                uint32_t a[4];
                ldmA(a, Ssu + (uint32_t)((wm + im * 16) * SST * 2 + ks * 32) + aoffS);
                mma_f16(oacc[im][0], a, bv[0], bv[1]);
                mma_f16(oacc[im][1], a, bv[2], bv[3]);
            }
        }
    }

    // Write O tile (half, scaled by 1/N)
#pragma unroll
    for (int im = 0; im < 2; im++) {
#pragma unroll
        for (int in = 0; in < 2; in++) {
#pragma unroll
            for (int hh = 0; hh < 2; hh++) {
                int n = qt * 64 + wm + im * 16 + er + 8 * hh;
                int j = h * HD + wnd + in * 8 + ec;
                __half2 o = __floats2half2_rn(oacc[im][in][2 * hh + 0] * inv_n,
                                              oacc[im][in][2 * hh + 1] * inv_n);
                *(__half2*)(g_ath + (size_t)(b * NN + n) * DD + j) = o;
            }
        }
    }
}

// ---------------------------------------------------------------------------
extern "C" void kernel_launch(void* const* d_in, const int* in_sizes, int n_in,
                              void* d_out, int out_size) {
    const float* x    = (const float*)d_in[0];
    const float* uvqk = (const float*)d_in[2];
    const float* ow   = (const float*)d_in[3];
    const float* ob   = (const float*)d_in[4];
    float* out = (float*)d_out;

    void *pxnh, *pmmh, *pwh, *powh;
    cudaGetSymbolAddress(&pxnh, g_xnh);
    cudaGetSymbolAddress(&pmmh, g_mmh);
    cudaGetSymbolAddress(&pwh,  g_wh);
    cudaGetSymbolAddress(&powh, g_owh);

    cudaFuncSetAttribute(gemm_h<0>, cudaFuncAttributeMaxDynamicSharedMemorySize, GSMEMH);
    cudaFuncSetAttribute(gemm_h<1>, cudaFuncAttributeMaxDynamicSharedMemorySize, GSMEMH);
    cudaFuncSetAttribute(attn_mma, cudaFuncAttributeMaxDynamicSharedMemorySize, ASMEM2);

    // 0. weight converts
    cvt_w_t<<<dim3(NC / 32, DD / 32), 256>>>(uvqk);
    cvt_ow<<<DD * DD / 1024, 256>>>(ow);
    // 1. xn = layernorm(x) -> half
    ln_kernel<<<RR, 128>>>(x);
    // 2. mm = silu(xn @ uvqk) -> half
    gemm_h<0><<<dim3(NC / 128, RR / 128), 256, GSMEMH>>>(
        (const __half*)pxnh, (const __half*)pwh, (__half*)pmmh, nullptr,
        nullptr, nullptr, NC, DD);
    // 3. attention (64-row q-tiles, 128-col KV macro-tiles, heavy blocks first)
    attn_mma<<<dim3(NN / 64, HH, BB), 256, ASMEM2>>>();
    // 4. o_input = u * layernorm(attn) -> half
    gated_ln_kernel<<<RR, 128>>>();
    // 5. out = o_input @ o_weight^T + bias + x -> fp32
    gemm_h<1><<<dim3(DD / 128, RR / 128), 256, GSMEMH>>>(
        (const __half*)pxnh, (const __half*)powh, nullptr, out, ob, x, DD, DD);
}

// round 15
// speedup vs baseline: 1.0666x; 1.0666x over previous
#include <cuda_runtime.h>
#include <cuda_fp16.h>
#include <cstdint>
#include <math.h>

// Problem constants
#define BB 4
#define NN 2048
#define DD 512
#define HH 8
#define HD 64
#define NC 2048
#define RR (BB*NN)

// Scratch (device globals; no allocation allowed)
__device__ __half g_xnh[(size_t)RR * DD];   // half: layernorm(x); later o_input
__device__ __half g_mmh[(size_t)RR * NC];   // half: silu(xn @ uvqk) [u|v|q|k]
__device__ __half g_wh [(size_t)NC * DD];   // half: uvqk transposed [n][k]
__device__ __half g_owh[(size_t)DD * DD];   // half: o_weight [n][k]
__device__ __half g_ath[(size_t)RR * DD];   // half attention output

__device__ __forceinline__ float silu_f(float v) {
    return v / (1.0f + __expf(-v));
}

// silu on a packed pair via tanh.approx.f16x2 (1 MUFU per 2 values)
__device__ __forceinline__ uint32_t silu_h2(float a, float b) {
    __half2 s = __floats2half2_rn(a, b);
    const __half2 hhalf = __floats2half2_rn(0.5f, 0.5f);
    __half2 hs = __hmul2(s, hhalf);
    uint32_t hsu = *(uint32_t*)&hs;
    uint32_t t;
    asm("tanh.approx.f16x2 %0, %1;" : "=r"(t) : "r"(hsu));
    __half2 th = *(__half2*)&t;
    __half2 sig = __hfma2(th, hhalf, hhalf);
    __half2 o = __hmul2(s, sig);
    return *(uint32_t*)&o;
}

__device__ __forceinline__ uint32_t smem_u32(const void* p) {
    uint32_t a;
    asm("{ .reg .u64 t; cvta.to.shared.u64 t, %1; cvt.u32.u64 %0, t; }"
        : "=r"(a) : "l"(p));
    return a;
}

__device__ __forceinline__ void ldmA(uint32_t* a, uint32_t addr) {
    asm volatile("ldmatrix.sync.aligned.m8n8.x4.shared.b16 {%0,%1,%2,%3}, [%4];"
                 : "=r"(a[0]), "=r"(a[1]), "=r"(a[2]), "=r"(a[3]) : "r"(addr));
}

__device__ __forceinline__ void ldmT(uint32_t* a, uint32_t addr) {
    asm volatile("ldmatrix.sync.aligned.m8n8.x4.trans.shared.b16 {%0,%1,%2,%3}, [%4];"
                 : "=r"(a[0]), "=r"(a[1]), "=r"(a[2]), "=r"(a[3]) : "r"(addr));
}

// fp16 mma, fp32 accumulate: D += A(16x16) * B(16x8)
__device__ __forceinline__ void mma_f16(float* d, const uint32_t* a,
                                        uint32_t b0, uint32_t b1) {
    asm volatile(
        "mma.sync.aligned.m16n8k16.row.col.f32.f16.f16.f32 "
        "{%0,%1,%2,%3},{%4,%5,%6,%7},{%8,%9},{%0,%1,%2,%3};"
        : "+f"(d[0]), "+f"(d[1]), "+f"(d[2]), "+f"(d[3])
        : "r"(a[0]), "r"(a[1]), "r"(a[2]), "r"(a[3]), "r"(b0), "r"(b1));
}

__device__ __forceinline__ void cp16(uint32_t dst, const void* src) {
    asm volatile("cp.async.cg.shared.global [%0], [%1], 16;" :: "r"(dst), "l"(src));
}
#define CP_COMMIT() asm volatile("cp.async.commit_group;" ::: "memory")
#define CP_WAIT(n)  asm volatile("cp.async.wait_group %0;" :: "n"(n) : "memory")

// ldmatrix-x4 per-lane byte offset for a 16x16-half A block, stride in halfs
__device__ __forceinline__ uint32_t ldm_off_h(int lane, int stride_halfs) {
    int r = (lane & 7) + ((lane >> 3) & 1) * 8;
    int c16 = (lane >> 4);
    return (uint32_t)(r * stride_halfs * 2 + c16 * 16);
}

// ldmatrix-x4 per-lane byte offset for B (K-major [n][k]): 2 n-frags x k16.
__device__ __forceinline__ uint32_t ldm_off_b(int lane, int stride_halfs) {
    int r = lane & 7;
    int m = lane >> 3;
    return (uint32_t)(((m >> 1) * 8 + r) * stride_halfs * 2 + (m & 1) * 16);
}

// ---------------------------------------------------------------------------
// LayerNorm: fp32 math, half output
// ---------------------------------------------------------------------------
__global__ void ln_kernel(const float* __restrict__ x) {
    int row = blockIdx.x;
    int t = threadIdx.x;
    float4 v = ((const float4*)(x + (size_t)row * DD))[t];
    float s  = v.x + v.y + v.z + v.w;
    float s2 = v.x*v.x + v.y*v.y + v.z*v.z + v.w*v.w;
#pragma unroll
    for (int o = 16; o > 0; o >>= 1) {
        s  += __shfl_xor_sync(0xffffffffu, s,  o);
        s2 += __shfl_xor_sync(0xffffffffu, s2, o);
    }
    __shared__ float sh[8];
    if ((t & 31) == 0) { sh[t >> 5] = s; sh[4 + (t >> 5)] = s2; }
    __syncthreads();
    s  = sh[0] + sh[1] + sh[2] + sh[3];
    s2 = sh[4] + sh[5] + sh[6] + sh[7];
    float mu  = s * (1.0f / DD);
    float var = fmaxf(s2 * (1.0f / DD) - mu * mu, 0.0f);
    float r   = rsqrtf(var + 1e-6f);
    __half2 h0 = __floats2half2_rn((v.x - mu) * r, (v.y - mu) * r);
    __half2 h1 = __floats2half2_rn((v.z - mu) * r, (v.w - mu) * r);
    ((__half2*)(g_xnh + (size_t)row * DD))[2 * t]     = h0;
    ((__half2*)(g_xnh + (size_t)row * DD))[2 * t + 1] = h1;
}

// Gated LN: reads half attention output, fp32 stats, half result
__global__ void gated_ln_kernel() {
    int row = blockIdx.x;
    int t = threadIdx.x;
    __half2 a01 = ((const __half2*)(g_ath + (size_t)row * DD))[2 * t];
    __half2 a23 = ((const __half2*)(g_ath + (size_t)row * DD))[2 * t + 1];
    float2 f0 = __half22float2(a01), f1 = __half22float2(a23);
    float s  = f0.x + f0.y + f1.x + f1.y;
    float s2 = f0.x*f0.x + f0.y*f0.y + f1.x*f1.x + f1.y*f1.y;
#pragma unroll
    for (int o = 16; o > 0; o >>= 1) {
        s  += __shfl_xor_sync(0xffffffffu, s,  o);
        s2 += __shfl_xor_sync(0xffffffffu, s2, o);
    }
    __shared__ float sh[8];
    if ((t & 31) == 0) { sh[t >> 5] = s; sh[4 + (t >> 5)] = s2; }
    __syncthreads();
    s  = sh[0] + sh[1] + sh[2] + sh[3];
    s2 = sh[4] + sh[5] + sh[6] + sh[7];
    float mu  = s * (1.0f / DD);
    float var = fmaxf(s2 * (1.0f / DD) - mu * mu, 0.0f);
    float r   = rsqrtf(var + 1e-6f);
    __half2 u01 = ((const __half2*)(g_mmh + (size_t)row * NC))[2 * t];
    __half2 u23 = ((const __half2*)(g_mmh + (size_t)row * NC))[2 * t + 1];
    float2 u0 = __half22float2(u01), u1 = __half22float2(u23);
    __half2 h0 = __floats2half2_rn(u0.x * (f0.x - mu) * r, u0.y * (f0.y - mu) * r);
    __half2 h1 = __floats2half2_rn(u1.x * (f1.x - mu) * r, u1.y * (f1.y - mu) * r);
    ((__half2*)(g_xnh + (size_t)row * DD))[2 * t]     = h0;
    ((__half2*)(g_xnh + (size_t)row * DD))[2 * t + 1] = h1;
}

// ---------------------------------------------------------------------------
// Weight converts
// ---------------------------------------------------------------------------
__global__ void cvt_w_t(const float* __restrict__ W) {
    __shared__ float tbuf[32][33];
    int lx = threadIdx.x & 31, ly = threadIdx.x >> 5;
    int bx = blockIdx.x, by = blockIdx.y;
    int col = bx * 32 + lx;
#pragma unroll
    for (int i = 0; i < 32; i += 8)
        tbuf[ly + i][lx] = W[(size_t)(by * 32 + ly + i) * NC + col];
    __syncthreads();
    int ok = by * 32 + lx;
#pragma unroll
    for (int i = 0; i < 32; i += 8)
        g_wh[(size_t)(bx * 32 + ly + i) * DD + ok] = __float2half_rn(tbuf[lx][ly + i]);
}

__global__ void cvt_ow(const float* __restrict__ W) {
    int i = blockIdx.x * 256 + threadIdx.x;
    float4 v = ((const float4*)W)[i];
    __half2 h0 = __floats2half2_rn(v.x, v.y);
    __half2 h1 = __floats2half2_rn(v.z, v.w);
    ((__half2*)g_owh)[2 * i]     = h0;
    ((__half2*)g_owh)[2 * i + 1] = h1;
}

// ---------------------------------------------------------------------------
// fp16 mma GEMM (R13 proven version: 2-stage, one sync per K-chunk)
// ---------------------------------------------------------------------------
#define SAH   72
#define ASBH  (128 * SAH * 2)
#define GSMEMH (4 * ASBH)

template <int MODE>
__global__ __launch_bounds__(256)
void gemm_h(const __half* __restrict__ A, const __half* __restrict__ Bm,
            __half* __restrict__ Ch, float* __restrict__ Cf,
            const float* __restrict__ bias, const float* __restrict__ xres,
            int Nn, int K) {
    extern __shared__ char smem[];
    uint32_t sAu = smem_u32(smem);
    uint32_t sBu = sAu + 2 * ASBH;

    int tid = threadIdx.x;
    int wid = tid >> 5, lane = tid & 31;
    int m0 = blockIdx.y * 128, n0 = blockIdx.x * 128;
    int wm = (wid & 1) * 64;
    int wn = (wid >> 1) * 32;

    float acc[4][4][4];
#pragma unroll
    for (int i = 0; i < 4; i++)
#pragma unroll
        for (int j = 0; j < 4; j++)
#pragma unroll
            for (int r = 0; r < 4; r++) acc[i][j][r] = 0.0f;

    const int NCH = K / 64;
    uint32_t aoff = ldm_off_h(lane, SAH);
    uint32_t boff = (uint32_t)(wn * SAH * 2) + ldm_off_b(lane, SAH);

    auto stageA = [&](int c, int s) {
#pragma unroll
        for (int i = 0; i < 4; i++) {
            int idx = tid + i * 256;
            int row = idx >> 3, seg = idx & 7;
            cp16(sAu + s * ASBH + (row * SAH + seg * 8) * 2,
                 A + (size_t)(m0 + row) * K + c * 64 + seg * 8);
        }
    };
    auto stageB = [&](int c, int s) {
#pragma unroll
        for (int i = 0; i < 4; i++) {
            int idx = tid + i * 256;
            int row = idx >> 3, seg = idx & 7;
            cp16(sBu + s * ASBH + (row * SAH + seg * 8) * 2,
                 Bm + (size_t)(n0 + row) * K + c * 64 + seg * 8);
        }
    };

    stageA(0, 0); stageB(0, 0); CP_COMMIT();

    for (int c = 0; c < NCH; c++) {
        int s = c & 1;
        CP_WAIT(0);
        __syncthreads();
        if (c + 1 < NCH) {
            stageA(c + 1, s ^ 1); stageB(c + 1, s ^ 1); CP_COMMIT();
        }

#pragma unroll
        for (int ks = 0; ks < 4; ks++) {
            uint32_t b01[4], b23[4];
            ldmA(b01, sBu + s * ASBH + boff + ks * 32);
            ldmA(b23, sBu + s * ASBH + boff + 16 * SAH * 2 + ks * 32);
#pragma unroll
            for (int im = 0; im < 4; im++) {
                uint32_t a[4];
                ldmA(a, sAu + s * ASBH + (uint32_t)((wm + im * 16) * SAH * 2 + ks * 32) + aoff);
                mma_f16(acc[im][0], a, b01[0], b01[1]);
                mma_f16(acc[im][1], a, b01[2], b01[3]);
                mma_f16(acc[im][2], a, b23[0], b23[1]);
                mma_f16(acc[im][3], a, b23[2], b23[3]);
            }
        }
    }

    int er = lane >> 2, ec = (lane & 3) * 2;
#pragma unroll
    for (int im = 0; im < 4; im++) {
#pragma unroll
        for (int in = 0; in < 4; in++) {
            int row = m0 + wm + im * 16 + er;
            int col = n0 + wn + in * 8 + ec;
#pragma unroll
            for (int h = 0; h < 2; h++) {
                float v0 = acc[im][in][2 * h + 0];
                float v1 = acc[im][in][2 * h + 1];
                int rr = row + 8 * h;
                if (MODE == 0) {
                    *(uint32_t*)(Ch + (size_t)rr * Nn + col) = silu_h2(v0, v1);
                } else {
                    float2 bi = *(const float2*)(bias + col);
                    float2 xr = *(const float2*)(xres + (size_t)rr * Nn + col);
                    float2 o; o.x = v0 + bi.x + xr.x; o.y = v1 + bi.y + xr.y;
                    *(float2*)(Cf + (size_t)rr * Nn + col) = o;
                }
            }
        }
    }
}

// ---------------------------------------------------------------------------
// Fused causal silu-attention, round 15: q-tile 64, 128-col KV macro-tiles,
// REGISTER-RESIDENT S. Warp = (strip = wid>>1 -> 16 q-rows, half = wid&1 ->
// 64 kv-cols). fp16 m16n8k16 C-frag layout == A-frag layout, so S stays in
// registers (mask+silu+pack in place, zero shuffles). Each warp accumulates
// a partial O over its kv-half; warp pairs are summed ONCE at the end via a
// padded smem buffer. Q A-frags hoisted into registers (loop-invariant).
// ONE sync per macro-tile. Smem: Q 9216 + K2[2] + V2[2] = 82944 -> 2 CTA/SM.
// ---------------------------------------------------------------------------
#define SAT2  72
#define QT2B  (64 * SAT2 * 2)             // 9216
#define KV2B  (128 * SAT2 * 2)            // 18432
#define AOFF_K2 QT2B
#define AOFF_V2 (QT2B + 2 * KV2B)
#define ASMEM2  (QT2B + 4 * KV2B)         // 82944
#define RSTR  66                          // reduction buffer row stride (floats)

__global__ __launch_bounds__(256, 2)
void attn_mma() {
    extern __shared__ char smem[];
    uint32_t sbase = smem_u32(smem);
    uint32_t Qsu = sbase;

    int qt = (int)(gridDim.x - 1 - blockIdx.x);   // heavy blocks first
    int h = blockIdx.y, b = blockIdx.z;
    int tid = threadIdx.x;
    int wid = tid >> 5, lane = tid & 31;
    int strip = wid >> 1;              // 4 strips x 16 q-rows
    int half  = wid & 1;               // kv-col half within macro-tile
    int wm = strip * 16;
    const int qcol = 1024 + h * HD;
    const int kcol = 1536 + h * HD;
    const int vcol = 512 + h * HD;
    uint32_t aoffQ = ldm_off_h(lane, SAT2);
    uint32_t koff = (uint32_t)((half * 64) * SAT2 * 2) + ldm_off_b(lane, SAT2);

    // V ldmatrix.x4.trans per-lane address pieces
    int tl = lane & 7;
    int tmi = lane >> 3;
    int tkr = (tmi & 1) * 8 + tl;
    int tnc = (tmi >> 1) * 8;

    auto stageQ = [&]() {
#pragma unroll
        for (int i = 0; i < 2; i++) {
            int idx = tid + i * 256;
            int row = idx >> 3, seg = idx & 7;
            cp16(Qsu + (row * SAT2 + seg * 8) * 2,
                 g_mmh + (size_t)(b * NN + qt * 64 + row) * NC + qcol + seg * 8);
        }
    };
    auto stageKV2 = [&](int kt2, int s) {
        uint32_t kd = sbase + AOFF_K2 + s * KV2B;
        uint32_t vd = sbase + AOFF_V2 + s * KV2B;
#pragma unroll
        for (int i = 0; i < 4; i++) {
            int idx = tid + i * 256;
            int row = idx >> 3, seg = idx & 7;
            size_t gb = (size_t)(b * NN + kt2 * 128 + row) * NC;
            uint32_t so = (uint32_t)((row * SAT2 + seg * 8) * 2);
            cp16(kd + so, g_mmh + gb + kcol + seg * 8);
            cp16(vd + so, g_mmh + gb + vcol + seg * 8);
        }
    };

    float oacc[8][4];                  // partial O: 16 rows x 64 d-cols
#pragma unroll
    for (int j = 0; j < 8; j++)
#pragma unroll
        for (int r = 0; r < 4; r++) oacc[j][r] = 0.0f;

    uint32_t aq[4][4];                 // loop-invariant Q fragments
    const float inv_n = 1.0f / (float)NN;
    int er = lane >> 2, ec = (lane & 3) * 2;
    const int nkt2 = (qt + 2) >> 1;

    stageQ(); stageKV2(0, 0); CP_COMMIT();

    for (int kt2 = 0; kt2 < nkt2; kt2++) {
        int s = kt2 & 1;
        CP_WAIT(0);
        __syncthreads();   // macro-tile kt2 visible; buffer s reusable

        if (kt2 + 1 < nkt2) { stageKV2(kt2 + 1, s ^ 1); CP_COMMIT(); }
        if (kt2 == 0) {
#pragma unroll
            for (int ks = 0; ks < 4; ks++)
                ldmA(aq[ks], Qsu + (uint32_t)(wm * SAT2 * 2 + ks * 32) + aoffQ);
        }

        uint32_t Ksu = sbase + AOFF_K2 + s * KV2B;
        uint32_t Vsu = sbase + AOFF_V2 + s * KV2B;

        // Phase 1: S[16 x 64] = Q_strip @ K_half^T (registers)
        float sacc[8][4];
#pragma unroll
        for (int j = 0; j < 8; j++)
#pragma unroll
            for (int r = 0; r < 4; r++) sacc[j][r] = 0.0f;
#pragma unroll
        for (int ks = 0; ks < 4; ks++) {
#pragma unroll
            for (int nb = 0; nb < 4; nb++) {
                uint32_t bk[4];
                ldmA(bk, Ksu + koff + (uint32_t)(nb * 16 * SAT2 * 2) + ks * 32);
                mma_f16(sacc[2 * nb + 0], aq[ks], bk[0], bk[1]);
                mma_f16(sacc[2 * nb + 1], aq[ks], bk[2], bk[3]);
            }
        }

        // mask (pre-silu; silu(0)==0) + fast silu + pack (registers only)
        bool need_mask = (kt2 == nkt2 - 1);
        int ig0 = qt * 64 + wm + er;
        int jb = kt2 * 128 + half * 64;
        uint32_t sh2[8][2];
#pragma unroll
        for (int in = 0; in < 8; in++) {
            int jg = jb + in * 8 + ec;
            float v0 = sacc[in][0], v1 = sacc[in][1];
            float v2 = sacc[in][2], v3 = sacc[in][3];
            if (need_mask) {
                if (jg > ig0)         v0 = 0.0f;
                if (jg + 1 > ig0)     v1 = 0.0f;
                if (jg > ig0 + 8)     v2 = 0.0f;
                if (jg + 1 > ig0 + 8) v3 = 0.0f;
            }
            sh2[in][0] = silu_h2(v0, v1);
            sh2[in][1] = silu_h2(v2, v3);
        }

        // Phase 2: O_partial += S @ V_half. A-frags = packed sacc (C-layout
        // of m16n8k16 == A-layout; k-lo block = n-frag 2ks, k-hi = 2ks+1).
#pragma unroll
        for (int ks = 0; ks < 4; ks++) {
            uint32_t a[4];
            a[0] = sh2[2 * ks + 0][0];
            a[1] = sh2[2 * ks + 0][1];
            a[2] = sh2[2 * ks + 1][0];
            a[3] = sh2[2 * ks + 1][1];
#pragma unroll
            for (int nb = 0; nb < 4; nb++) {
                uint32_t bv[4];
                ldmT(bv, Vsu + (uint32_t)(((half * 64 + ks * 16 + tkr) * SAT2 + nb * 16 + tnc) * 2));
                mma_f16(oacc[2 * nb + 0], a, bv[0], bv[1]);
                mma_f16(oacc[2 * nb + 1], a, bv[2], bv[3]);
            }
        }
    }

    // Pair reduction: odd-half warps store partial O; even-half warps add and
    // write. Reuses smem (loop is finished after this barrier).
    __syncthreads();
    float* Rbuf = (float*)smem;        // [64 rows][RSTR] fp32 = 16896 B
    if (half == 1) {
#pragma unroll
        for (int in = 0; in < 8; in++) {
#pragma unroll
            for (int hh = 0; hh < 2; hh++) {
                int row = wm + er + 8 * hh;
                int col = in * 8 + ec;
                float2 p; p.x = oacc[in][2 * hh + 0]; p.y = oacc[in][2 * hh + 1];
                *(float2*)(Rbuf + row * RSTR + col) = p;
            }
        }
    }
    __syncthreads();
    if (half == 0) {
#pragma unroll
        for (int in = 0; in < 8; in++) {
#pragma unroll
            for (int hh = 0; hh < 2; hh++) {
                int row = wm + er + 8 * hh;
                int col = in * 8 + ec;
                float2 p = *(const float2*)(Rbuf + row * RSTR + col);
                __half2 o = __floats2half2_rn(
                    (oacc[in][2 * hh + 0] + p.x) * inv_n,
                    (oacc[in][2 * hh + 1] + p.y) * inv_n);
                *(__half2*)(g_ath + (size_t)(b * NN + qt * 64 + row) * DD
                            + h * HD + col) = o;
            }
        }
    }
}

// ---------------------------------------------------------------------------
extern "C" void kernel_launch(void* const* d_in, const int* in_sizes, int n_in,
                              void* d_out, int out_size) {
    const float* x    = (const float*)d_in[0];
    const float* uvqk = (const float*)d_in[2];
    const float* ow   = (const float*)d_in[3];
    const float* ob   = (const float*)d_in[4];
    float* out = (float*)d_out;

    void *pxnh, *pmmh, *pwh, *powh;
    cudaGetSymbolAddress(&pxnh, g_xnh);
    cudaGetSymbolAddress(&pmmh, g_mmh);
    cudaGetSymbolAddress(&pwh,  g_wh);
    cudaGetSymbolAddress(&powh, g_owh);

    cudaFuncSetAttribute(gemm_h<0>, cudaFuncAttributeMaxDynamicSharedMemorySize, GSMEMH);
    cudaFuncSetAttribute(gemm_h<1>, cudaFuncAttributeMaxDynamicSharedMemorySize, GSMEMH);
    cudaFuncSetAttribute(attn_mma, cudaFuncAttributeMaxDynamicSharedMemorySize, ASMEM2);

    // 0. weight converts
    cvt_w_t<<<dim3(NC / 32, DD / 32), 256>>>(uvqk);
    cvt_ow<<<DD * DD / 1024, 256>>>(ow);
    // 1. xn = layernorm(x) -> half
    ln_kernel<<<RR, 128>>>(x);
    // 2. mm = silu(xn @ uvqk) -> half
    gemm_h<0><<<dim3(NC / 128, RR / 128), 256, GSMEMH>>>(
        (const __half*)pxnh, (const __half*)pwh, (__half*)pmmh, nullptr,
        nullptr, nullptr, NC, DD);
    // 3. attention (q64 tiles, 128-col macro-tiles, register-resident S)
    attn_mma<<<dim3(NN / 64, HH, BB), 256, ASMEM2>>>();
    // 4. o_input = u * layernorm(attn) -> half
    gated_ln_kernel<<<RR, 128>>>();
    // 5. out = o_input @ o_weight^T + bias + x -> fp32
    gemm_h<1><<<dim3(DD / 128, RR / 128), 256, GSMEMH>>>(
        (const __half*)pxnh, (const __half*)powh, nullptr, out, ob, x, DD, DD);
}